// round 14
// baseline (speedup 1.0000x reference)
#include <cuda_runtime.h>
#include <cuda_bf16.h>
#include <math.h>

#define D 128
#define NH 4
#define MAXN 100352
#define MAXE 1700000
#define LDS_W 136  // padded bf16 row stride (272B -> conflict-free ldmatrix)
#define TILE_ELEMS (128 * LDS_W)

// ---------------- scratch (static device globals; no allocations) -------------
__device__ float g_xl[MAXN * D];
__device__ float g_xr[MAXN * D];
__device__ float g_h[MAXN * D];
__device__ int   g_src[MAXE];
__device__ int   g_counts[MAXN];
__device__ int   g_starts[MAXN];
__device__ int   g_cursor[MAXN];
__device__ int   g_bsum[128];
__device__ int   g_boff[128];
__device__ int   g_is64;
// pre-converted weights: per layer [WLhi][WLlo][WRhi][WRlo], padded LDS_W layout
__device__ __nv_bfloat16 g_wbf[2 * 4 * TILE_ELEMS];

// ---------------- zero counts + edge dtype detection -------------------------
__global__ void k_zerodetect(const unsigned int* __restrict__ e, int n) {
    int i = blockIdx.x * blockDim.x + threadIdx.x;
    if (i < n) g_counts[i] = 0;
    if (blockIdx.x == 0 && threadIdx.x < 32) {
        unsigned int w = e[2 * threadIdx.x + 1];
        unsigned int b = __ballot_sync(0xffffffffu, w == 0u);
        if (threadIdx.x == 0) g_is64 = (b == 0xffffffffu) ? 1 : 0;
    }
}

__device__ __forceinline__ int edge_at(const void* e, int is64, long long idx) {
    if (is64) return (int)((const long long*)e)[idx];
    return ((const int*)e)[idx];
}

__global__ void k_hist(const void* __restrict__ e, long long E) {
    long long i = (long long)blockIdx.x * blockDim.x + threadIdx.x;
    if (i >= E) return;
    int is64 = g_is64;
    int d = edge_at(e, is64, E + i);
    atomicAdd(&g_counts[d], 1);
}

// ---- hierarchical scan ------------------------------------------------------
__global__ __launch_bounds__(256) void k_blksum(int n) {
    __shared__ int sh[256];
    int b = blockIdx.x, t = threadIdx.x;
    int base = b * 1024;
    int s = 0;
#pragma unroll
    for (int j = 0; j < 4; j++) {
        int i = base + t + j * 256;
        if (i < n) s += g_counts[i];
    }
    sh[t] = s;
    __syncthreads();
    for (int off = 128; off >= 1; off >>= 1) {
        if (t < off) sh[t] += sh[t + off];
        __syncthreads();
    }
    if (t == 0) g_bsum[b] = sh[0];
}

__global__ __launch_bounds__(128) void k_scan2(int nb) {
    __shared__ int sh[128];
    int t = threadIdx.x;
    sh[t] = (t < nb) ? g_bsum[t] : 0;
    __syncthreads();
    if (t == 0) {
        int run = 0;
        for (int i = 0; i < nb; i++) {
            int c = sh[i];
            g_boff[i] = run;
            run += c;
        }
    }
}

__global__ __launch_bounds__(256) void k_starts(int n) {
    __shared__ int ssum[256];
    int b = blockIdx.x, t = threadIdx.x;
    int base = b * 1024 + t * 4;
    int c0 = 0, c1 = 0, c2 = 0, c3 = 0;
    if (base + 0 < n) c0 = g_counts[base + 0];
    if (base + 1 < n) c1 = g_counts[base + 1];
    if (base + 2 < n) c2 = g_counts[base + 2];
    if (base + 3 < n) c3 = g_counts[base + 3];
    ssum[t] = c0 + c1 + c2 + c3;
    __syncthreads();
    for (int off = 1; off < 256; off <<= 1) {
        int v = (t >= off) ? ssum[t - off] : 0;
        __syncthreads();
        ssum[t] += v;
        __syncthreads();
    }
    int run = g_boff[b] + ((t == 0) ? 0 : ssum[t - 1]);
    if (base + 0 < n) { g_starts[base + 0] = run; g_cursor[base + 0] = run; run += c0; }
    if (base + 1 < n) { g_starts[base + 1] = run; g_cursor[base + 1] = run; run += c1; }
    if (base + 2 < n) { g_starts[base + 2] = run; g_cursor[base + 2] = run; run += c2; }
    if (base + 3 < n) { g_starts[base + 3] = run; g_cursor[base + 3] = run; run += c3; }
}

__global__ void k_scatter(const void* __restrict__ e, long long E) {
    long long i = (long long)blockIdx.x * blockDim.x + threadIdx.x;
    if (i >= E) return;
    int is64 = g_is64;
    int s = edge_at(e, is64, i);
    int d = edge_at(e, is64, E + i);
    int pos = atomicAdd(&g_cursor[d], 1);
    g_src[pos] = s;
}

// ---------------- bf16 hi/lo conversion helpers ------------------------------
__device__ __forceinline__ void cvt_store4(__nv_bfloat16* hi, __nv_bfloat16* lo,
                                           int addr, float4 v) {
    __nv_bfloat16 h0 = __float2bfloat16(v.x), h1 = __float2bfloat16(v.y);
    __nv_bfloat16 h2 = __float2bfloat16(v.z), h3 = __float2bfloat16(v.w);
    __nv_bfloat16 l0 = __float2bfloat16(v.x - __bfloat162float(h0));
    __nv_bfloat16 l1 = __float2bfloat16(v.y - __bfloat162float(h1));
    __nv_bfloat16 l2 = __float2bfloat16(v.z - __bfloat162float(h2));
    __nv_bfloat16 l3 = __float2bfloat16(v.w - __bfloat162float(h3));
    *(__nv_bfloat162*)&hi[addr] = __nv_bfloat162(h0, h1);
    *(__nv_bfloat162*)&hi[addr + 2] = __nv_bfloat162(h2, h3);
    *(__nv_bfloat162*)&lo[addr] = __nv_bfloat162(l0, l1);
    *(__nv_bfloat162*)&lo[addr + 2] = __nv_bfloat162(l2, l3);
}

// pre-convert weights into the exact smem image (padded LDS_W layout)
__global__ __launch_bounds__(256) void k_wconv(const float* __restrict__ Wl,
                                               const float* __restrict__ Wr) {
    int o = blockIdx.x;  // 0=WL 1=WR
    int l = blockIdx.y;  // layer
    const float* W = (o ? Wr : Wl) + l * D * D;
    __nv_bfloat16* hi = g_wbf + ((l * 4) + o * 2) * TILE_ELEMS;
    __nv_bfloat16* lo = hi + TILE_ELEMS;
    int tid = threadIdx.x;
#pragma unroll
    for (int j = 0; j < 16; j++) {
        int idx = tid + j * 256;  // 4096 float4 = 128 x 32
        int k = idx >> 5, n4 = (idx & 31) * 4;
        float4 v = ((const float4*)W)[idx];
        cvt_store4(hi, lo, k * LDS_W + n4, v);
    }
}

// ---------------- tensor-core GEMM (bf16 3-split): xl & xr fused -------------
__device__ __forceinline__ void ldsm4(unsigned* r, unsigned addr) {
    asm volatile("ldmatrix.sync.aligned.m8n8.x4.shared.b16 {%0,%1,%2,%3}, [%4];"
                 : "=r"(r[0]), "=r"(r[1]), "=r"(r[2]), "=r"(r[3]) : "r"(addr));
}
__device__ __forceinline__ void ldsm4t(unsigned* r, unsigned addr) {
    asm volatile("ldmatrix.sync.aligned.m8n8.x4.trans.shared.b16 {%0,%1,%2,%3}, [%4];"
                 : "=r"(r[0]), "=r"(r[1]), "=r"(r[2]), "=r"(r[3]) : "r"(addr));
}
__device__ __forceinline__ void mma_bf16(float* c, const unsigned* a, unsigned b0,
                                         unsigned b1) {
    asm volatile(
        "mma.sync.aligned.m16n8k16.row.col.f32.bf16.bf16.f32 "
        "{%0,%1,%2,%3}, {%4,%5,%6,%7}, {%8,%9}, {%0,%1,%2,%3};"
        : "+f"(c[0]), "+f"(c[1]), "+f"(c[2]), "+f"(c[3])
        : "r"(a[0]), "r"(a[1]), "r"(a[2]), "r"(a[3]), "r"(b0), "r"(b1));
}

// smem bf16 layout: [AHI][ALO][WL_HI][WL_LO][WR_HI][WR_LO], each 128*136
#define SMEM_BYTES (6 * TILE_ELEMS * 2)

// Persistent CTAs: weight image copied into smem ONCE per CTA, then loop over
// 128-row tiles. 512 threads = 16 warps (8m x 2n).
__global__ __launch_bounds__(512, 1) void k_gemm_tc(const float* __restrict__ A_ext,
                                                    int a_internal, int layer,
                                                    int M, int ntiles) {
    extern __shared__ __nv_bfloat16 sm[];
    __nv_bfloat16* sAhi = sm;
    __nv_bfloat16* sAlo = sm + TILE_ELEMS;
    const float* A = a_internal ? g_h : A_ext;
    int tid = threadIdx.x;

    // copy pre-converted weights ONCE (4*TILE_ELEMS bf16 = 8704 uint4)
    {
        const uint4* wsrc = (const uint4*)(g_wbf + layer * 4 * TILE_ELEMS);
        uint4* wdst = (uint4*)(sm + 2 * TILE_ELEMS);
#pragma unroll
        for (int j = 0; j < 17; j++) wdst[tid + j * 512] = wsrc[tid + j * 512];
    }

    int lane = tid & 31, w = tid >> 5;
    int wm = w & 7, wn = w >> 3;  // warp tile: rows wm*16, cols wn*64
    int r8 = lane & 7, s01 = (lane >> 3) & 1, sk = lane >> 4;
    unsigned base = (unsigned)__cvta_generic_to_shared(sm);

    for (int tile = blockIdx.x; tile < ntiles; tile += gridDim.x) {
        int row0 = tile * 128;
        __syncthreads();  // prior iteration's LDSM reads done before overwrite
        // convert A tile (128 rows = 4096 float4), zero-padded past M
#pragma unroll
        for (int j = 0; j < 8; j++) {
            int idx = tid + j * 512;
            int r = idx >> 5, c4 = (idx & 31) * 4;
            float4 v = make_float4(0.f, 0.f, 0.f, 0.f);
            if (row0 + r < M)
                v = ((const float4*)(A + (long long)(row0 + r) * D))[idx & 31];
            cvt_store4(sAhi, sAlo, r * LDS_W + c4, v);
        }
        __syncthreads();

        float c[2][8][4];
#pragma unroll
        for (int o = 0; o < 2; o++)
#pragma unroll
            for (int j = 0; j < 8; j++)
#pragma unroll
                for (int q = 0; q < 4; q++) c[o][j][q] = 0.f;

        for (int ks = 0; ks < 8; ks++) {
            int k0 = ks * 16;
            unsigned ahi[4], alo[4];
            {
                int row = wm * 16 + s01 * 8 + r8;
                int col = k0 + sk * 8;
                unsigned off = (unsigned)(row * LDS_W + col) * 2u;
                ldsm4(ahi, base + off);
                ldsm4(alo, base + TILE_ELEMS * 2 + off);
            }
#pragma unroll
            for (int o = 0; o < 2; o++) {
#pragma unroll
                for (int jj = 0; jj < 4; jj++) {
                    int n0 = wn * 64 + jj * 16;
                    int rowk = k0 + s01 * 8 + r8;
                    int coln = n0 + sk * 8;
                    unsigned woff = (unsigned)(rowk * LDS_W + coln) * 2u;
                    unsigned bhi[4], blo[4];
                    ldsm4t(bhi, base + (2 + o * 2) * TILE_ELEMS * 2 + woff);
                    ldsm4t(blo, base + (3 + o * 2) * TILE_ELEMS * 2 + woff);
                    mma_bf16(c[o][jj * 2], ahi, bhi[0], bhi[1]);
                    mma_bf16(c[o][jj * 2], ahi, blo[0], blo[1]);
                    mma_bf16(c[o][jj * 2], alo, bhi[0], bhi[1]);
                    mma_bf16(c[o][jj * 2 + 1], ahi, bhi[2], bhi[3]);
                    mma_bf16(c[o][jj * 2 + 1], ahi, blo[2], blo[3]);
                    mma_bf16(c[o][jj * 2 + 1], alo, bhi[2], bhi[3]);
                }
            }
        }

        // epilogue
#pragma unroll
        for (int o = 0; o < 2; o++) {
            float* Out = o ? g_xr : g_xl;
            int row = row0 + wm * 16 + (lane >> 2);
#pragma unroll
            for (int j = 0; j < 8; j++) {
                int col = wn * 64 + j * 8 + (lane & 3) * 2;
                if (row < M)
                    *(float2*)&Out[(long long)row * D + col] =
                        make_float2(c[o][j][0], c[o][j][1]);
                if (row + 8 < M)
                    *(float2*)&Out[(long long)(row + 8) * D + col] =
                        make_float2(c[o][j][2], c[o][j][3]);
            }
        }
    }
}

// ---------------- fused edge attention + aggregate + LN + ELU + residual -----
// Max-free softmax in base-2: att pre-scaled by log2(e), p = ex2(alpha2).
__device__ __forceinline__ float ex2(float x) {
    float r;
    asm("ex2.approx.ftz.f32 %0, %1;" : "=f"(r) : "f"(x));
    return r;
}

__device__ __forceinline__ float edge_alpha(float4 xl4, float4 xr4, float4 at4) {
    float t0 = xl4.x + xr4.x; t0 = fmaxf(t0, 0.2f * t0);
    float t1 = xl4.y + xr4.y; t1 = fmaxf(t1, 0.2f * t1);
    float t2 = xl4.z + xr4.z; t2 = fmaxf(t2, 0.2f * t2);
    float t3 = xl4.w + xr4.w; t3 = fmaxf(t3, 0.2f * t3);
    float p = t0 * at4.x + t1 * at4.y + t2 * at4.z + t3 * at4.w;
    p += __shfl_xor_sync(0xffffffffu, p, 1);
    p += __shfl_xor_sync(0xffffffffu, p, 2);
    p += __shfl_xor_sync(0xffffffffu, p, 4);
    return p;
}

struct AccState { float s, a0, a1, a2, a3; };

__device__ __forceinline__ void upd(AccState& st, float4 cur, float4 xr4,
                                    float4 at4) {
    float p = ex2(edge_alpha(cur, xr4, at4));
    st.s += p;
    st.a0 += p * cur.x;
    st.a1 += p * cur.y;
    st.a2 += p * cur.z;
    st.a3 += p * cur.w;
}

// One warp per node; 4-deep register prefetch, 2 accumulator states.
// Steady loop: single branch, 4 unguarded loads in flight (MLP=4).
__global__ __launch_bounds__(256) void k_edge(const float* __restrict__ hin_ext,
                                              int hin_internal,
                                              float* __restrict__ hout_ext,
                                              int hout_internal,
                                              const float* __restrict__ att,
                                              const float* __restrict__ bias,
                                              const float* __restrict__ gamma,
                                              const float* __restrict__ beta,
                                              int n) {
    int node = (blockIdx.x * blockDim.x + threadIdx.x) >> 5;
    int lane = threadIdx.x & 31;
    if (node >= n) return;
    const float* hin = hin_internal ? g_h : hin_ext;
    float* hout = hout_internal ? g_h : hout_ext;
    const int c0 = lane * 4;

    float4 xr4 = *(const float4*)&g_xr[(long long)node * D + c0];
    float4 at4 = *(const float4*)&att[c0];
    const float LOG2E = 1.4426950408889634f;
    at4.x *= LOG2E; at4.y *= LOG2E; at4.z *= LOG2E; at4.w *= LOG2E;

    int beg = g_starts[node];
    int cnt = g_counts[node];

    // prefetch first 4 (guarded)
    float4 b0 = make_float4(0.f, 0.f, 0.f, 0.f), b1 = b0, b2 = b0, b3 = b0;
    if (cnt > 0) b0 = *(const float4*)&g_xl[(long long)g_src[beg + 0] * D + c0];
    if (cnt > 1) b1 = *(const float4*)&g_xl[(long long)g_src[beg + 1] * D + c0];
    if (cnt > 2) b2 = *(const float4*)&g_xl[(long long)g_src[beg + 2] * D + c0];
    if (cnt > 3) b3 = *(const float4*)&g_xl[(long long)g_src[beg + 3] * D + c0];

    // self-loop while the first gathers fly
    float4 xv = *(const float4*)&g_xl[(long long)node * D + c0];
    AccState s0, s1;
    {
        float p = ex2(edge_alpha(xv, xr4, at4));
        s0.s = p;
        s0.a0 = p * xv.x; s0.a1 = p * xv.y; s0.a2 = p * xv.z; s0.a3 = p * xv.w;
    }
    s1.s = 0.f; s1.a0 = 0.f; s1.a1 = 0.f; s1.a2 = 0.f; s1.a3 = 0.f;

    int k = 0;
    for (; k + 8 <= cnt; k += 4) {
        float4 c0v = b0, c1v = b1, c2v = b2, c3v = b3;
        b0 = *(const float4*)&g_xl[(long long)g_src[beg + k + 4] * D + c0];
        b1 = *(const float4*)&g_xl[(long long)g_src[beg + k + 5] * D + c0];
        b2 = *(const float4*)&g_xl[(long long)g_src[beg + k + 6] * D + c0];
        b3 = *(const float4*)&g_xl[(long long)g_src[beg + k + 7] * D + c0];
        upd(s0, c0v, xr4, at4);
        upd(s1, c1v, xr4, at4);
        upd(s0, c2v, xr4, at4);
        upd(s1, c3v, xr4, at4);
    }
    // tail: issue remaining (<=3) loads first, then drain buffers, then tail
    {
        float4 t0 = make_float4(0.f, 0.f, 0.f, 0.f), t1 = t0, t2 = t0;
        if (k + 4 < cnt) t0 = *(const float4*)&g_xl[(long long)g_src[beg + k + 4] * D + c0];
        if (k + 5 < cnt) t1 = *(const float4*)&g_xl[(long long)g_src[beg + k + 5] * D + c0];
        if (k + 6 < cnt) t2 = *(const float4*)&g_xl[(long long)g_src[beg + k + 6] * D + c0];
        if (k + 0 < cnt) upd(s0, b0, xr4, at4);
        if (k + 1 < cnt) upd(s1, b1, xr4, at4);
        if (k + 2 < cnt) upd(s0, b2, xr4, at4);
        if (k + 3 < cnt) upd(s1, b3, xr4, at4);
        if (k + 4 < cnt) upd(s0, t0, xr4, at4);
        if (k + 5 < cnt) upd(s1, t1, xr4, at4);
        if (k + 6 < cnt) upd(s0, t2, xr4, at4);
    }

    float s = s0.s + s1.s;
    float a0 = s0.a0 + s1.a0;
    float a1 = s0.a1 + s1.a1;
    float a2 = s0.a2 + s1.a2;
    float a3 = s0.a3 + s1.a3;

    float4 bi4 = *(const float4*)&bias[c0];
    float inv = 1.0f / s;
    float gg0 = a0 * inv + bi4.x;
    float gg1 = a1 * inv + bi4.y;
    float gg2 = a2 * inv + bi4.z;
    float gg3 = a3 * inv + bi4.w;

    float lsum = gg0 + gg1 + gg2 + gg3;
#pragma unroll
    for (int off = 16; off >= 1; off >>= 1) lsum += __shfl_xor_sync(0xffffffffu, lsum, off);
    float mean = lsum * (1.0f / 128.0f);
    float d0 = gg0 - mean, d1 = gg1 - mean, d2 = gg2 - mean, d3 = gg3 - mean;
    float lsq = d0 * d0 + d1 * d1 + d2 * d2 + d3 * d3;
#pragma unroll
    for (int off = 16; off >= 1; off >>= 1) lsq += __shfl_xor_sync(0xffffffffu, lsq, off);
    float var = lsq * (1.0f / 128.0f);
    float rstd = rsqrtf(var + 1e-5f);

    float4 ga4 = *(const float4*)&gamma[c0];
    float4 be4 = *(const float4*)&beta[c0];
    float y0 = d0 * rstd * ga4.x + be4.x;
    float y1 = d1 * rstd * ga4.y + be4.y;
    float y2 = d2 * rstd * ga4.z + be4.z;
    float y3 = d3 * rstd * ga4.w + be4.w;
    y0 = (y0 > 0.f) ? y0 : expm1f(y0);
    y1 = (y1 > 0.f) ? y1 : expm1f(y1);
    y2 = (y2 > 0.f) ? y2 : expm1f(y2);
    y3 = (y3 > 0.f) ? y3 : expm1f(y3);

    float4 hv = *(const float4*)&hin[(long long)node * D + c0];
    float4 o;
    o.x = hv.x + y0;
    o.y = hv.y + y1;
    o.z = hv.z + y2;
    o.w = hv.w + y3;
    *(float4*)&hout[(long long)node * D + c0] = o;
}

// ---------------- launch ------------------------------------------------------
extern "C" void kernel_launch(void* const* d_in, const int* in_sizes, int n_in,
                              void* d_out, int out_size) {
    const float* x = (const float*)d_in[0];
    const void* ei = (const void*)d_in[1];
    const float* Wl = (const float*)d_in[2];
    const float* Wr = (const float*)d_in[3];
    const float* att = (const float*)d_in[4];
    const float* bias = (const float*)d_in[5];
    const float* gamma = (const float*)d_in[6];
    const float* beta = (const float*)d_in[7];
    float* out = (float*)d_out;

    int N = in_sizes[0] / D;
    long long E = (long long)in_sizes[1] / 2;
    int nb = (N + 1023) / 1024;

    // one-time idempotent config (first call is the uncaptured correctness run)
    static cudaStream_t s2 = nullptr;
    static cudaEvent_t evFork = nullptr, evSort = nullptr;
    static int nsm = 0;
    if (!s2) {
        cudaFuncSetAttribute(k_gemm_tc, cudaFuncAttributeMaxDynamicSharedMemorySize,
                             SMEM_BYTES);
        cudaStreamCreateWithFlags(&s2, cudaStreamNonBlocking);
        cudaEventCreateWithFlags(&evFork, cudaEventDisableTiming);
        cudaEventCreateWithFlags(&evSort, cudaEventDisableTiming);
        int dev = 0;
        cudaGetDevice(&dev);
        if (cudaDeviceGetAttribute(&nsm, cudaDevAttrMultiProcessorCount, dev) !=
                cudaSuccess || nsm <= 0)
            nsm = 148;
    }

    int eg = (int)((E + 255) / 256);
    int ntiles = (N + 127) / 128;
    int gg = (nsm < ntiles) ? nsm : ntiles;
    int ewarps = (N + 7) / 8;

    // fork: sort chain on s2, weights+gemm0 on the main stream
    cudaEventRecord(evFork, 0);
    cudaStreamWaitEvent(s2, evFork, 0);

    k_zerodetect<<<(N + 255) / 256, 256, 0, s2>>>((const unsigned int*)ei, N);
    k_hist<<<eg, 256, 0, s2>>>(ei, E);
    k_wconv<<<dim3(2, 2), 256>>>(Wl, Wr);
    k_gemm_tc<<<gg, 512, SMEM_BYTES>>>(x, 0, 0, N, ntiles);
    k_blksum<<<nb, 256, 0, s2>>>(N);
    k_scan2<<<1, 128, 0, s2>>>(nb);
    k_starts<<<nb, 256, 0, s2>>>(N);
    k_scatter<<<eg, 256, 0, s2>>>(ei, E);
    cudaEventRecord(evSort, s2);

    // join: edge0 needs gemm0 (main) + sort (s2)
    cudaStreamWaitEvent(0, evSort, 0);

    k_edge<<<ewarps, 256>>>(x, 0, out, 1, att, bias, gamma, beta, N);
    k_gemm_tc<<<gg, 512, SMEM_BYTES>>>(x, 1, 1, N, ntiles);
    k_edge<<<ewarps, 256>>>(x, 1, out, 0, att + NH * 32, bias + D, gamma + D,
                            beta + D, N);
}

// round 15
// speedup vs baseline: 1.0576x; 1.0576x over previous
#include <cuda_runtime.h>
#include <cuda_bf16.h>
#include <math.h>

#define D 128
#define NH 4
#define MAXN 100352
#define MAXE 1700000
#define LDS_W 136  // padded bf16 row stride (272B -> conflict-free ldmatrix)
#define TILE_ELEMS (128 * LDS_W)    // one 128x128 weight image
#define A64_ELEMS (64 * LDS_W)      // one 64-row A image

// ---------------- scratch (static device globals; no allocations) -------------
__device__ float g_xl[MAXN * D];
__device__ float g_xr[MAXN * D];
__device__ float g_h[MAXN * D];
__device__ int   g_src[MAXE];
__device__ int   g_counts[MAXN];
__device__ int   g_starts[MAXN];
__device__ int   g_cursor[MAXN];
__device__ int   g_bsum[128];
__device__ int   g_boff[128];
__device__ int   g_is64;
// pre-converted weights: per layer [WLhi][WLlo][WRhi][WRlo], padded LDS_W layout
__device__ __nv_bfloat16 g_wbf[2 * 4 * TILE_ELEMS];

// ---------------- zero counts + edge dtype detection -------------------------
__global__ void k_zerodetect(const unsigned int* __restrict__ e, int n) {
    int i = blockIdx.x * blockDim.x + threadIdx.x;
    if (i < n) g_counts[i] = 0;
    if (blockIdx.x == 0 && threadIdx.x < 32) {
        unsigned int w = e[2 * threadIdx.x + 1];
        unsigned int b = __ballot_sync(0xffffffffu, w == 0u);
        if (threadIdx.x == 0) g_is64 = (b == 0xffffffffu) ? 1 : 0;
    }
}

__device__ __forceinline__ int edge_at(const void* e, int is64, long long idx) {
    if (is64) return (int)((const long long*)e)[idx];
    return ((const int*)e)[idx];
}

__global__ void k_hist(const void* __restrict__ e, long long E) {
    long long i = (long long)blockIdx.x * blockDim.x + threadIdx.x;
    if (i >= E) return;
    int is64 = g_is64;
    int d = edge_at(e, is64, E + i);
    atomicAdd(&g_counts[d], 1);
}

// ---- hierarchical scan ------------------------------------------------------
__global__ __launch_bounds__(256) void k_blksum(int n) {
    __shared__ int sh[256];
    int b = blockIdx.x, t = threadIdx.x;
    int base = b * 1024;
    int s = 0;
#pragma unroll
    for (int j = 0; j < 4; j++) {
        int i = base + t + j * 256;
        if (i < n) s += g_counts[i];
    }
    sh[t] = s;
    __syncthreads();
    for (int off = 128; off >= 1; off >>= 1) {
        if (t < off) sh[t] += sh[t + off];
        __syncthreads();
    }
    if (t == 0) g_bsum[b] = sh[0];
}

__global__ __launch_bounds__(128) void k_scan2(int nb) {
    __shared__ int sh[128];
    int t = threadIdx.x;
    sh[t] = (t < nb) ? g_bsum[t] : 0;
    __syncthreads();
    if (t == 0) {
        int run = 0;
        for (int i = 0; i < nb; i++) {
            int c = sh[i];
            g_boff[i] = run;
            run += c;
        }
    }
}

__global__ __launch_bounds__(256) void k_starts(int n) {
    __shared__ int ssum[256];
    int b = blockIdx.x, t = threadIdx.x;
    int base = b * 1024 + t * 4;
    int c0 = 0, c1 = 0, c2 = 0, c3 = 0;
    if (base + 0 < n) c0 = g_counts[base + 0];
    if (base + 1 < n) c1 = g_counts[base + 1];
    if (base + 2 < n) c2 = g_counts[base + 2];
    if (base + 3 < n) c3 = g_counts[base + 3];
    ssum[t] = c0 + c1 + c2 + c3;
    __syncthreads();
    for (int off = 1; off < 256; off <<= 1) {
        int v = (t >= off) ? ssum[t - off] : 0;
        __syncthreads();
        ssum[t] += v;
        __syncthreads();
    }
    int run = g_boff[b] + ((t == 0) ? 0 : ssum[t - 1]);
    if (base + 0 < n) { g_starts[base + 0] = run; g_cursor[base + 0] = run; run += c0; }
    if (base + 1 < n) { g_starts[base + 1] = run; g_cursor[base + 1] = run; run += c1; }
    if (base + 2 < n) { g_starts[base + 2] = run; g_cursor[base + 2] = run; run += c2; }
    if (base + 3 < n) { g_starts[base + 3] = run; g_cursor[base + 3] = run; run += c3; }
}

__global__ void k_scatter(const void* __restrict__ e, long long E) {
    long long i = (long long)blockIdx.x * blockDim.x + threadIdx.x;
    if (i >= E) return;
    int is64 = g_is64;
    int s = edge_at(e, is64, i);
    int d = edge_at(e, is64, E + i);
    int pos = atomicAdd(&g_cursor[d], 1);
    g_src[pos] = s;
}

// ---------------- bf16 hi/lo conversion helpers ------------------------------
__device__ __forceinline__ void cvt_store4(__nv_bfloat16* hi, __nv_bfloat16* lo,
                                           int addr, float4 v) {
    __nv_bfloat16 h0 = __float2bfloat16(v.x), h1 = __float2bfloat16(v.y);
    __nv_bfloat16 h2 = __float2bfloat16(v.z), h3 = __float2bfloat16(v.w);
    __nv_bfloat16 l0 = __float2bfloat16(v.x - __bfloat162float(h0));
    __nv_bfloat16 l1 = __float2bfloat16(v.y - __bfloat162float(h1));
    __nv_bfloat16 l2 = __float2bfloat16(v.z - __bfloat162float(h2));
    __nv_bfloat16 l3 = __float2bfloat16(v.w - __bfloat162float(h3));
    *(__nv_bfloat162*)&hi[addr] = __nv_bfloat162(h0, h1);
    *(__nv_bfloat162*)&hi[addr + 2] = __nv_bfloat162(h2, h3);
    *(__nv_bfloat162*)&lo[addr] = __nv_bfloat162(l0, l1);
    *(__nv_bfloat162*)&lo[addr + 2] = __nv_bfloat162(l2, l3);
}

// pre-convert weights into the exact smem image (padded LDS_W layout)
__global__ __launch_bounds__(256) void k_wconv(const float* __restrict__ Wl,
                                               const float* __restrict__ Wr) {
    int o = blockIdx.x;  // 0=WL 1=WR
    int l = blockIdx.y;  // layer
    const float* W = (o ? Wr : Wl) + l * D * D;
    __nv_bfloat16* hi = g_wbf + ((l * 4) + o * 2) * TILE_ELEMS;
    __nv_bfloat16* lo = hi + TILE_ELEMS;
    int tid = threadIdx.x;
#pragma unroll
    for (int j = 0; j < 16; j++) {
        int idx = tid + j * 256;  // 4096 float4 = 128 x 32
        int k = idx >> 5, n4 = (idx & 31) * 4;
        float4 v = ((const float4*)W)[idx];
        cvt_store4(hi, lo, k * LDS_W + n4, v);
    }
}

// ---------------- tensor-core GEMM (bf16 3-split), split by output -----------
__device__ __forceinline__ void ldsm4(unsigned* r, unsigned addr) {
    asm volatile("ldmatrix.sync.aligned.m8n8.x4.shared.b16 {%0,%1,%2,%3}, [%4];"
                 : "=r"(r[0]), "=r"(r[1]), "=r"(r[2]), "=r"(r[3]) : "r"(addr));
}
__device__ __forceinline__ void ldsm4t(unsigned* r, unsigned addr) {
    asm volatile("ldmatrix.sync.aligned.m8n8.x4.trans.shared.b16 {%0,%1,%2,%3}, [%4];"
                 : "=r"(r[0]), "=r"(r[1]), "=r"(r[2]), "=r"(r[3]) : "r"(addr));
}
__device__ __forceinline__ void mma_bf16(float* c, const unsigned* a, unsigned b0,
                                         unsigned b1) {
    asm volatile(
        "mma.sync.aligned.m16n8k16.row.col.f32.bf16.bf16.f32 "
        "{%0,%1,%2,%3}, {%4,%5,%6,%7}, {%8,%9}, {%0,%1,%2,%3};"
        : "+f"(c[0]), "+f"(c[1]), "+f"(c[2]), "+f"(c[3])
        : "r"(a[0]), "r"(a[1]), "r"(a[2]), "r"(a[3]), "r"(b0), "r"(b1));
}

// smem bf16 layout per CTA: [A_HI 64x136][A_LO][W_HI 128x136][W_LO]
// = (2*A64 + 2*TILE) * 2B = 34816 + 69632 = 104448 B  -> 2 CTAs/SM
#define GSM_A_HI 0
#define GSM_A_LO (A64_ELEMS)
#define GSM_W    (2 * A64_ELEMS)
#define SMEM_BYTES ((2 * A64_ELEMS + 2 * TILE_ELEMS) * 2)

// Persistent CTAs; blockIdx.y = o (0 -> xl/WL, 1 -> xr/WR). 64-row tiles,
// 256 threads = 8 warps (4m x 2n), warp tile 16x64.
__global__ __launch_bounds__(256, 2) void k_gemm_tc(const float* __restrict__ A_ext,
                                                    int a_internal, int layer,
                                                    int M, int ntiles) {
    extern __shared__ __nv_bfloat16 sm[];
    __nv_bfloat16* sAhi = sm + GSM_A_HI;
    __nv_bfloat16* sAlo = sm + GSM_A_LO;
    const float* A = a_internal ? g_h : A_ext;
    int tid = threadIdx.x;
    int o = blockIdx.y;
    float* Out = o ? g_xr : g_xl;

    // copy this output's pre-converted W hi/lo ONCE (2*TILE_ELEMS bf16 = 4352 uint4)
    {
        const uint4* wsrc = (const uint4*)(g_wbf + (layer * 4 + o * 2) * TILE_ELEMS);
        uint4* wdst = (uint4*)(sm + GSM_W);
#pragma unroll
        for (int j = 0; j < 17; j++) wdst[tid + j * 256] = wsrc[tid + j * 256];
    }

    int lane = tid & 31, w = tid >> 5;
    int wm = w & 3, wn = w >> 2;  // warp tile: rows wm*16, cols wn*64
    int r8 = lane & 7, s01 = (lane >> 3) & 1, sk = lane >> 4;
    unsigned base = (unsigned)__cvta_generic_to_shared(sm);

    for (int tile = blockIdx.x; tile < ntiles; tile += gridDim.x) {
        int row0 = tile * 64;
        __syncthreads();  // prior iteration's LDSM reads done before overwrite
        // convert A tile (64 rows = 2048 float4), zero-padded past M
#pragma unroll
        for (int j = 0; j < 8; j++) {
            int idx = tid + j * 256;
            int r = idx >> 5, c4 = (idx & 31) * 4;
            float4 v = make_float4(0.f, 0.f, 0.f, 0.f);
            if (row0 + r < M)
                v = ((const float4*)(A + (long long)(row0 + r) * D))[idx & 31];
            cvt_store4(sAhi, sAlo, r * LDS_W + c4, v);
        }
        __syncthreads();

        float c[8][4];
#pragma unroll
        for (int j = 0; j < 8; j++)
#pragma unroll
            for (int q = 0; q < 4; q++) c[j][q] = 0.f;

        for (int ks = 0; ks < 8; ks++) {
            int k0 = ks * 16;
            unsigned ahi[4], alo[4];
            {
                int row = wm * 16 + s01 * 8 + r8;
                int col = k0 + sk * 8;
                unsigned off = (unsigned)(row * LDS_W + col) * 2u;
                ldsm4(ahi, base + off);
                ldsm4(alo, base + (unsigned)(GSM_A_LO * 2) + off);
            }
#pragma unroll
            for (int jj = 0; jj < 4; jj++) {
                int n0 = wn * 64 + jj * 16;
                int rowk = k0 + s01 * 8 + r8;
                int coln = n0 + sk * 8;
                unsigned woff = (unsigned)(rowk * LDS_W + coln) * 2u;
                unsigned bhi[4], blo[4];
                ldsm4t(bhi, base + (unsigned)(GSM_W * 2) + woff);
                ldsm4t(blo, base + (unsigned)((GSM_W + TILE_ELEMS) * 2) + woff);
                mma_bf16(c[jj * 2], ahi, bhi[0], bhi[1]);
                mma_bf16(c[jj * 2], ahi, blo[0], blo[1]);
                mma_bf16(c[jj * 2], alo, bhi[0], bhi[1]);
                mma_bf16(c[jj * 2 + 1], ahi, bhi[2], bhi[3]);
                mma_bf16(c[jj * 2 + 1], ahi, blo[2], blo[3]);
                mma_bf16(c[jj * 2 + 1], alo, bhi[2], bhi[3]);
            }
        }

        // epilogue
        {
            int row = row0 + wm * 16 + (lane >> 2);
#pragma unroll
            for (int j = 0; j < 8; j++) {
                int col = wn * 64 + j * 8 + (lane & 3) * 2;
                if (row < M)
                    *(float2*)&Out[(long long)row * D + col] =
                        make_float2(c[j][0], c[j][1]);
                if (row + 8 < M)
                    *(float2*)&Out[(long long)(row + 8) * D + col] =
                        make_float2(c[j][2], c[j][3]);
            }
        }
    }
}

// ---------------- fused edge attention + aggregate + LN + ELU + residual -----
// Max-free softmax in base-2: att pre-scaled by log2(e), p = ex2(alpha2).
__device__ __forceinline__ float ex2(float x) {
    float r;
    asm("ex2.approx.ftz.f32 %0, %1;" : "=f"(r) : "f"(x));
    return r;
}

__device__ __forceinline__ float edge_alpha(float4 xl4, float4 xr4, float4 at4) {
    float t0 = xl4.x + xr4.x; t0 = fmaxf(t0, 0.2f * t0);
    float t1 = xl4.y + xr4.y; t1 = fmaxf(t1, 0.2f * t1);
    float t2 = xl4.z + xr4.z; t2 = fmaxf(t2, 0.2f * t2);
    float t3 = xl4.w + xr4.w; t3 = fmaxf(t3, 0.2f * t3);
    float p = t0 * at4.x + t1 * at4.y + t2 * at4.z + t3 * at4.w;
    p += __shfl_xor_sync(0xffffffffu, p, 1);
    p += __shfl_xor_sync(0xffffffffu, p, 2);
    p += __shfl_xor_sync(0xffffffffu, p, 4);
    return p;
}

struct AccState { float s, a0, a1, a2, a3; };

__device__ __forceinline__ void upd(AccState& st, float4 cur, float4 xr4,
                                    float4 at4) {
    float p = ex2(edge_alpha(cur, xr4, at4));
    st.s += p;
    st.a0 += p * cur.x;
    st.a1 += p * cur.y;
    st.a2 += p * cur.z;
    st.a3 += p * cur.w;
}

__global__ __launch_bounds__(256) void k_edge(const float* __restrict__ hin_ext,
                                              int hin_internal,
                                              float* __restrict__ hout_ext,
                                              int hout_internal,
                                              const float* __restrict__ att,
                                              const float* __restrict__ bias,
                                              const float* __restrict__ gamma,
                                              const float* __restrict__ beta,
                                              int n) {
    int node = (blockIdx.x * blockDim.x + threadIdx.x) >> 5;
    int lane = threadIdx.x & 31;
    if (node >= n) return;
    const float* hin = hin_internal ? g_h : hin_ext;
    float* hout = hout_internal ? g_h : hout_ext;
    const int c0 = lane * 4;

    float4 xr4 = *(const float4*)&g_xr[(long long)node * D + c0];
    float4 at4 = *(const float4*)&att[c0];
    const float LOG2E = 1.4426950408889634f;
    at4.x *= LOG2E; at4.y *= LOG2E; at4.z *= LOG2E; at4.w *= LOG2E;

    // self-loop
    float4 xv = *(const float4*)&g_xl[(long long)node * D + c0];
    AccState s0, s1;
    {
        float p = ex2(edge_alpha(xv, xr4, at4));
        s0.s = p;
        s0.a0 = p * xv.x; s0.a1 = p * xv.y; s0.a2 = p * xv.z; s0.a3 = p * xv.w;
    }
    s1.s = 0.f; s1.a0 = 0.f; s1.a1 = 0.f; s1.a2 = 0.f; s1.a3 = 0.f;

    int beg = g_starts[node];
    int cnt = g_counts[node];

    float4 pf0 = make_float4(0.f, 0.f, 0.f, 0.f);
    float4 pf1 = make_float4(0.f, 0.f, 0.f, 0.f);
    if (cnt > 0) pf0 = *(const float4*)&g_xl[(long long)g_src[beg] * D + c0];
    if (cnt > 1) pf1 = *(const float4*)&g_xl[(long long)g_src[beg + 1] * D + c0];

    int k = 0;
    for (; k + 1 < cnt; k += 2) {
        float4 c0v = pf0, c1v = pf1;
        if (k + 2 < cnt) pf0 = *(const float4*)&g_xl[(long long)g_src[beg + k + 2] * D + c0];
        if (k + 3 < cnt) pf1 = *(const float4*)&g_xl[(long long)g_src[beg + k + 3] * D + c0];
        upd(s0, c0v, xr4, at4);
        upd(s1, c1v, xr4, at4);
    }
    if (k < cnt) upd(s0, pf0, xr4, at4);

    float s = s0.s + s1.s;
    float a0 = s0.a0 + s1.a0;
    float a1 = s0.a1 + s1.a1;
    float a2 = s0.a2 + s1.a2;
    float a3 = s0.a3 + s1.a3;

    float4 bi4 = *(const float4*)&bias[c0];
    float inv = 1.0f / s;
    float gg0 = a0 * inv + bi4.x;
    float gg1 = a1 * inv + bi4.y;
    float gg2 = a2 * inv + bi4.z;
    float gg3 = a3 * inv + bi4.w;

    float lsum = gg0 + gg1 + gg2 + gg3;
#pragma unroll
    for (int off = 16; off >= 1; off >>= 1) lsum += __shfl_xor_sync(0xffffffffu, lsum, off);
    float mean = lsum * (1.0f / 128.0f);
    float d0 = gg0 - mean, d1 = gg1 - mean, d2 = gg2 - mean, d3 = gg3 - mean;
    float lsq = d0 * d0 + d1 * d1 + d2 * d2 + d3 * d3;
#pragma unroll
    for (int off = 16; off >= 1; off >>= 1) lsq += __shfl_xor_sync(0xffffffffu, lsq, off);
    float var = lsq * (1.0f / 128.0f);
    float rstd = rsqrtf(var + 1e-5f);

    float4 ga4 = *(const float4*)&gamma[c0];
    float4 be4 = *(const float4*)&beta[c0];
    float y0 = d0 * rstd * ga4.x + be4.x;
    float y1 = d1 * rstd * ga4.y + be4.y;
    float y2 = d2 * rstd * ga4.z + be4.z;
    float y3 = d3 * rstd * ga4.w + be4.w;
    y0 = (y0 > 0.f) ? y0 : expm1f(y0);
    y1 = (y1 > 0.f) ? y1 : expm1f(y1);
    y2 = (y2 > 0.f) ? y2 : expm1f(y2);
    y3 = (y3 > 0.f) ? y3 : expm1f(y3);

    float4 hv = *(const float4*)&hin[(long long)node * D + c0];
    float4 o;
    o.x = hv.x + y0;
    o.y = hv.y + y1;
    o.z = hv.z + y2;
    o.w = hv.w + y3;
    *(float4*)&hout[(long long)node * D + c0] = o;
}

// ---------------- launch ------------------------------------------------------
extern "C" void kernel_launch(void* const* d_in, const int* in_sizes, int n_in,
                              void* d_out, int out_size) {
    const float* x = (const float*)d_in[0];
    const void* ei = (const void*)d_in[1];
    const float* Wl = (const float*)d_in[2];
    const float* Wr = (const float*)d_in[3];
    const float* att = (const float*)d_in[4];
    const float* bias = (const float*)d_in[5];
    const float* gamma = (const float*)d_in[6];
    const float* beta = (const float*)d_in[7];
    float* out = (float*)d_out;

    int N = in_sizes[0] / D;
    long long E = (long long)in_sizes[1] / 2;
    int nb = (N + 1023) / 1024;

    // one-time idempotent config (first call is the uncaptured correctness run)
    static cudaStream_t s2 = nullptr;
    static cudaEvent_t evFork = nullptr, evSort = nullptr;
    static int nsm = 0;
    if (!s2) {
        cudaFuncSetAttribute(k_gemm_tc, cudaFuncAttributeMaxDynamicSharedMemorySize,
                             SMEM_BYTES);
        cudaStreamCreateWithFlags(&s2, cudaStreamNonBlocking);
        cudaEventCreateWithFlags(&evFork, cudaEventDisableTiming);
        cudaEventCreateWithFlags(&evSort, cudaEventDisableTiming);
        int dev = 0;
        cudaGetDevice(&dev);
        if (cudaDeviceGetAttribute(&nsm, cudaDevAttrMultiProcessorCount, dev) !=
                cudaSuccess || nsm <= 0)
            nsm = 148;
    }

    int eg = (int)((E + 255) / 256);
    int ntiles = (N + 63) / 64;
    int gx = (nsm < ntiles) ? nsm : ntiles;
    dim3 gg(gx, 2);
    int ewarps = (N + 7) / 8;

    // fork: sort chain on s2, weights+gemm0 on the main stream
    cudaEventRecord(evFork, 0);
    cudaStreamWaitEvent(s2, evFork, 0);

    k_zerodetect<<<(N + 255) / 256, 256, 0, s2>>>((const unsigned int*)ei, N);
    k_hist<<<eg, 256, 0, s2>>>(ei, E);
    k_wconv<<<dim3(2, 2), 256>>>(Wl, Wr);
    k_gemm_tc<<<gg, 256, SMEM_BYTES>>>(x, 0, 0, N, ntiles);
    k_blksum<<<nb, 256, 0, s2>>>(N);
    k_scan2<<<1, 128, 0, s2>>>(nb);
    k_starts<<<nb, 256, 0, s2>>>(N);
    k_scatter<<<eg, 256, 0, s2>>>(ei, E);
    cudaEventRecord(evSort, s2);

    // join: edge0 needs gemm0 (main) + sort (s2)
    cudaStreamWaitEvent(0, evSort, 0);

    k_edge<<<ewarps, 256>>>(x, 0, out, 1, att, bias, gamma, beta, N);
    k_gemm_tc<<<gg, 256, SMEM_BYTES>>>(x, 1, 1, N, ntiles);
    k_edge<<<ewarps, 256>>>(x, 1, out, 0, att + NH * 32, bias + D, gamma + D,
                            beta + D, N);
}